// round 1
// baseline (speedup 1.0000x reference)
#include <cuda_runtime.h>
#include <math.h>

// ---------------------------------------------------------------------------
// GIN_37048387895934: 3-layer GIN (eps=0) + BN + sum-pool + linear + log_softmax
// Shapes (from reference): N=524288 nodes x 16 feats, E=8388608 edges,
// hidden DIM=32, 8192 graphs x 64 nodes, output [8192,2] float32.
// ---------------------------------------------------------------------------

#define NFEAT 16
#define HDIM 32
#define NPG 64
#define BN_EPS 1e-5f

static constexpr int MAX_NODES = 8192 * 64;      // 524288

// Scratch (allocation-free rule: __device__ globals)
__device__ float g_bufT[(size_t)MAX_NODES * HDIM];  // pre-BN layer output
__device__ float g_bufH[(size_t)MAX_NODES * HDIM];  // normalized features
__device__ float g_agg [(size_t)MAX_NODES * HDIM];  // neighbor sums
__device__ float g_stats[2 * HDIM];                  // [0:32) sum, [32:64) sumsq

// ---------------------------------------------------------------------------
// Vector reduction to global memory (sm_90+): 1 instruction per 16B
// ---------------------------------------------------------------------------
__device__ __forceinline__ void red_add_v4(float* p, float4 v) {
    asm volatile("red.global.add.v4.f32 [%0], {%1,%2,%3,%4};"
                 :: "l"(p), "f"(v.x), "f"(v.y), "f"(v.z), "f"(v.w)
                 : "memory");
}

// ---------------------------------------------------------------------------
// Scatter: agg[dst] += h[src], one thread per edge, DIN/4 x red.v4
// ---------------------------------------------------------------------------
template <int DIN>
__global__ void scatter_kernel(const float* __restrict__ h,
                               const int* __restrict__ src,
                               const int* __restrict__ dst,
                               float* __restrict__ agg, int n_edges) {
    int e = blockIdx.x * blockDim.x + threadIdx.x;
    if (e >= n_edges) return;
    int s = src[e];
    int d = dst[e];
    const float4* hp = reinterpret_cast<const float4*>(h + (size_t)s * DIN);
    float* ap = agg + (size_t)d * DIN;
#pragma unroll
    for (int i = 0; i < DIN / 4; i++) {
        float4 v = hp[i];
        red_add_v4(ap + i * 4, v);
    }
}

// ---------------------------------------------------------------------------
// Per-node MLP: t = x + agg; u = relu(t@Wa + ba); v = relu(u@Wb + bb)
// Writes v to out and accumulates per-channel sum/sumsq for BN (fused).
// One thread per node; 256 threads/block. Shared tile padded to 33 floats/row
// for bank-conflict-free column reduction.
// ---------------------------------------------------------------------------
template <int DIN>
__global__ void mlp_kernel(const float* __restrict__ xin,
                           const float* __restrict__ agg,
                           const float* __restrict__ Wa,
                           const float* __restrict__ ba,
                           const float* __restrict__ Wb,
                           const float* __restrict__ bb,
                           float* __restrict__ out,
                           float* __restrict__ stats, int n_nodes) {
    __shared__ float sWa[DIN * HDIM];
    __shared__ float sWb[HDIM * HDIM];
    __shared__ float sba[HDIM], sbb[HDIM];
    __shared__ float tile[256 * 33];
    __shared__ float ps[8 * 32], pq[8 * 32];

    for (int i = threadIdx.x; i < DIN * HDIM; i += blockDim.x) sWa[i] = Wa[i];
    for (int i = threadIdx.x; i < HDIM * HDIM; i += blockDim.x) sWb[i] = Wb[i];
    if (threadIdx.x < HDIM) {
        sba[threadIdx.x] = ba[threadIdx.x];
        sbb[threadIdx.x] = bb[threadIdx.x];
    }
    __syncthreads();

    int node = blockIdx.x * 256 + threadIdx.x;
    bool valid = (node < n_nodes);

    if (valid) {
        float t[DIN];
        const float4* xp = reinterpret_cast<const float4*>(xin + (size_t)node * DIN);
        const float4* ap = reinterpret_cast<const float4*>(agg + (size_t)node * DIN);
#pragma unroll
        for (int i = 0; i < DIN / 4; i++) {
            float4 a = xp[i];
            float4 b = ap[i];
            t[4 * i + 0] = a.x + b.x;
            t[4 * i + 1] = a.y + b.y;
            t[4 * i + 2] = a.z + b.z;
            t[4 * i + 3] = a.w + b.w;
        }
        float u[HDIM];
#pragma unroll
        for (int j = 0; j < HDIM; j++) u[j] = sba[j];
#pragma unroll
        for (int i = 0; i < DIN; i++) {
            float ti = t[i];
#pragma unroll
            for (int j = 0; j < HDIM; j++) u[j] = fmaf(ti, sWa[i * HDIM + j], u[j]);
        }
#pragma unroll
        for (int j = 0; j < HDIM; j++) u[j] = fmaxf(u[j], 0.0f);

        float* op = out + (size_t)node * HDIM;
        float4 acc;
#pragma unroll
        for (int j = 0; j < HDIM; j++) {
            float v = sbb[j];
#pragma unroll
            for (int i = 0; i < HDIM; i++) v = fmaf(u[i], sWb[i * HDIM + j], v);
            v = fmaxf(v, 0.0f);                     // outer relu before BN
            tile[threadIdx.x * 33 + j] = v;
            ((&acc.x)[j & 3]) = v;
            if ((j & 3) == 3) {
                *reinterpret_cast<float4*>(op + (j - 3)) = acc;
            }
        }
    } else {
#pragma unroll
        for (int j = 0; j < HDIM; j++) tile[threadIdx.x * 33 + j] = 0.0f;
    }
    __syncthreads();

    // Column reduction for BN stats (conflict-free via 33-float row pitch)
    int c = threadIdx.x & 31;
    int r0 = threadIdx.x >> 5;  // 0..7
    float s = 0.0f, q = 0.0f;
#pragma unroll
    for (int k = 0; k < 32; k++) {
        float v = tile[(r0 * 32 + k) * 33 + c];
        s += v;
        q += v * v;
    }
    ps[r0 * 32 + c] = s;
    pq[r0 * 32 + c] = q;
    __syncthreads();
    if (threadIdx.x < 32) {
        float ss = 0.0f, qq = 0.0f;
#pragma unroll
        for (int k = 0; k < 8; k++) {
            ss += ps[k * 32 + threadIdx.x];
            qq += pq[k * 32 + threadIdx.x];
        }
        atomicAdd(&stats[threadIdx.x], ss);
        atomicAdd(&stats[32 + threadIdx.x], qq);
    }
}

// ---------------------------------------------------------------------------
// BN normalize: out = gamma*(v-m)*rsqrt(var+eps)+beta, elementwise (float4)
// ---------------------------------------------------------------------------
__global__ void bn_kernel(const float* __restrict__ in, float* __restrict__ out,
                          const float* __restrict__ stats,
                          const float* __restrict__ gamma,
                          const float* __restrict__ beta,
                          float invN, int n_vec4) {
    __shared__ float sc[32], sh[32];
    if (threadIdx.x < 32) {
        float m = stats[threadIdx.x] * invN;
        float var = stats[32 + threadIdx.x] * invN - m * m;
        float s = gamma[threadIdx.x] * rsqrtf(var + BN_EPS);
        sc[threadIdx.x] = s;
        sh[threadIdx.x] = beta[threadIdx.x] - m * s;
    }
    __syncthreads();
    int stride = gridDim.x * blockDim.x;
    for (int i = blockIdx.x * blockDim.x + threadIdx.x; i < n_vec4; i += stride) {
        int cb = (i & 7) * 4;  // channel base: (i*4) % 32
        float4 v = reinterpret_cast<const float4*>(in)[i];
        float4 r;
        r.x = fmaf(v.x, sc[cb + 0], sh[cb + 0]);
        r.y = fmaf(v.y, sc[cb + 1], sh[cb + 1]);
        r.z = fmaf(v.z, sc[cb + 2], sh[cb + 2]);
        r.w = fmaf(v.w, sc[cb + 3], sh[cb + 3]);
        reinterpret_cast<float4*>(out)[i] = r;
    }
}

// ---------------------------------------------------------------------------
// Pool (sum over 64 nodes) + final linear (32->2) + log_softmax.
// One warp per graph; lane = channel.
// ---------------------------------------------------------------------------
__global__ void pool_kernel(const float* __restrict__ h,
                            const float* __restrict__ Wf,
                            const float* __restrict__ bf,
                            float* __restrict__ out, int n_graphs) {
    int gwarp = (blockIdx.x * blockDim.x + threadIdx.x) >> 5;
    int lane = threadIdx.x & 31;
    if (gwarp >= n_graphs) return;
    const float* base = h + (size_t)gwarp * NPG * HDIM;
    float s = 0.0f;
#pragma unroll 8
    for (int n = 0; n < NPG; n++) s += base[n * HDIM + lane];
    float p0 = s * Wf[lane * 2 + 0];
    float p1 = s * Wf[lane * 2 + 1];
#pragma unroll
    for (int off = 16; off > 0; off >>= 1) {
        p0 += __shfl_xor_sync(0xFFFFFFFFu, p0, off);
        p1 += __shfl_xor_sync(0xFFFFFFFFu, p1, off);
    }
    if (lane == 0) {
        float l0 = p0 + bf[0];
        float l1 = p1 + bf[1];
        float m = fmaxf(l0, l1);
        float lse = m + logf(expf(l0 - m) + expf(l1 - m));
        out[gwarp * 2 + 0] = l0 - lse;
        out[gwarp * 2 + 1] = l1 - lse;
    }
}

// ---------------------------------------------------------------------------
// Launch
// ---------------------------------------------------------------------------
extern "C" void kernel_launch(void* const* d_in, const int* in_sizes, int n_in,
                              void* d_out, int out_size) {
    const float* x   = (const float*)d_in[0];
    const int*   ei  = (const int*)d_in[1];
    // d_in[2] = batch scalar (unused; derived from sizes)
    const float* W1a = (const float*)d_in[3];
    const float* b1a = (const float*)d_in[4];
    const float* W1b = (const float*)d_in[5];
    const float* b1b = (const float*)d_in[6];
    const float* W2a = (const float*)d_in[7];
    const float* b2a = (const float*)d_in[8];
    const float* W2b = (const float*)d_in[9];
    const float* b2b = (const float*)d_in[10];
    const float* W3a = (const float*)d_in[11];
    const float* b3a = (const float*)d_in[12];
    const float* W3b = (const float*)d_in[13];
    const float* b3b = (const float*)d_in[14];
    const float* g1  = (const float*)d_in[15];
    const float* be1 = (const float*)d_in[16];
    const float* g2  = (const float*)d_in[17];
    const float* be2 = (const float*)d_in[18];
    const float* g3  = (const float*)d_in[19];
    const float* be3 = (const float*)d_in[20];
    const float* Wf  = (const float*)d_in[21];
    const float* bf  = (const float*)d_in[22];
    float* out = (float*)d_out;

    int n_nodes  = in_sizes[0] / NFEAT;
    int n_edges  = in_sizes[1] / 2;
    int n_graphs = n_nodes / NPG;
    const int* src = ei;
    const int* dst = ei + n_edges;

    float *bufT, *bufH, *agg, *stats;
    cudaGetSymbolAddress((void**)&bufT, g_bufT);
    cudaGetSymbolAddress((void**)&bufH, g_bufH);
    cudaGetSymbolAddress((void**)&agg, g_agg);
    cudaGetSymbolAddress((void**)&stats, g_stats);

    dim3 blk(256);
    int grid_e = (n_edges + 255) / 256;
    int grid_n = (n_nodes + 255) / 256;
    int grid_bn = 2048;
    int n_vec4 = n_nodes * HDIM / 4;
    float invN = 1.0f / (float)n_nodes;

    // ---- Layer 1 (DIN=16) ----
    cudaMemsetAsync(agg, 0, (size_t)n_nodes * NFEAT * sizeof(float), 0);
    cudaMemsetAsync(stats, 0, 2 * HDIM * sizeof(float), 0);
    scatter_kernel<NFEAT><<<grid_e, blk>>>(x, src, dst, agg, n_edges);
    mlp_kernel<NFEAT><<<grid_n, blk>>>(x, agg, W1a, b1a, W1b, b1b, bufT, stats, n_nodes);
    bn_kernel<<<grid_bn, blk>>>(bufT, bufH, stats, g1, be1, invN, n_vec4);

    // ---- Layer 2 (DIN=32) ----
    cudaMemsetAsync(agg, 0, (size_t)n_nodes * HDIM * sizeof(float), 0);
    cudaMemsetAsync(stats, 0, 2 * HDIM * sizeof(float), 0);
    scatter_kernel<HDIM><<<grid_e, blk>>>(bufH, src, dst, agg, n_edges);
    mlp_kernel<HDIM><<<grid_n, blk>>>(bufH, agg, W2a, b2a, W2b, b2b, bufT, stats, n_nodes);
    bn_kernel<<<grid_bn, blk>>>(bufT, bufH, stats, g2, be2, invN, n_vec4);

    // ---- Layer 3 (DIN=32) ----
    cudaMemsetAsync(agg, 0, (size_t)n_nodes * HDIM * sizeof(float), 0);
    cudaMemsetAsync(stats, 0, 2 * HDIM * sizeof(float), 0);
    scatter_kernel<HDIM><<<grid_e, blk>>>(bufH, src, dst, agg, n_edges);
    mlp_kernel<HDIM><<<grid_n, blk>>>(bufH, agg, W3a, b3a, W3b, b3b, bufT, stats, n_nodes);
    bn_kernel<<<grid_bn, blk>>>(bufT, bufH, stats, g3, be3, invN, n_vec4);

    // ---- Pool + head ----
    int grid_p = (n_graphs * 32 + 255) / 256;
    pool_kernel<<<grid_p, blk>>>(bufH, Wf, bf, out, n_graphs);
}